// round 2
// baseline (speedup 1.0000x reference)
#include <cuda_runtime.h>
#include <math.h>

// Problem constants (fixed by the dataset)
constexpr int Nn  = 50000;
constexpr int Ee  = 800000;
constexpr int CIN = 16;
constexpr int CO  = 64;

// ---------------- device scratch (static allocation; no cudaMalloc) ----------
__device__ int   g_is64;
__device__ float g_deg[Nn];
__device__ float g_dinv[Nn];
__device__ int   g_cnt[Nn];
__device__ int   g_rowptr[Nn + 1];
__device__ int   g_fill[Nn];
__device__ int   g_csrc[Ee];
__device__ float g_cw[Ee];

__device__ float g_tx1[Nn * CIN];
__device__ float g_tx2[Nn * CIN];
__device__ float g_th1[Nn * CO];
__device__ float g_th2[Nn * CO];
__device__ float g_hr [Nn * CO];
__device__ float g_tr1[Nn * CO];
__device__ float g_tr2[Nn * CO];
__device__ float g_xpre[Nn * 3 * CO];  // [N,192] gate-major cols: z|r|htil
__device__ float g_z  [Nn * CO];

// ---------------- edge-index dtype detection ---------------------------------
// If the buffer really is int64 (values < 2^31, non-negative), every high
// 32-bit word is zero. For int32 data those words are subsequent indices
// (random in [0, 50000)) — P(512 consecutive zeros) ~ 0.
__global__ void k_detect(const unsigned* __restrict__ ei_raw) {
    if (blockIdx.x == 0 && threadIdx.x == 0) {
        int is64 = 1;
        for (int i = 0; i < 512; i++) {
            if (ei_raw[2 * i + 1] != 0u) { is64 = 0; break; }
        }
        g_is64 = is64;
    }
}

__device__ __forceinline__ void load_edge(const void* ei, int e, int& s, int& d) {
    if (g_is64) {
        const long long* p = (const long long*)ei;
        s = (int)p[e];
        d = (int)p[Ee + e];
    } else {
        const int* p = (const int*)ei;
        s = p[e];
        d = p[Ee + e];
    }
}

// ---------------- preprocessing ----------------------------------------------
__global__ void k_zero() {
    int i = blockIdx.x * blockDim.x + threadIdx.x;
    if (i < Nn) { g_deg[i] = 0.f; g_cnt[i] = 0; }
}

__global__ void k_degcnt(const void* __restrict__ ei,
                         const float* __restrict__ ew) {
    int e = blockIdx.x * blockDim.x + threadIdx.x;
    if (e >= Ee) return;
    int s, d;
    load_edge(ei, e, s, d);
    float w = ew[e];
    if (s != d) atomicAdd(&g_deg[s], w);
    atomicAdd(&g_cnt[d], 1);
}

__global__ void k_dinv() {
    int i = blockIdx.x * blockDim.x + threadIdx.x;
    if (i >= Nn) return;
    float d = g_deg[i];
    g_dinv[i] = (d > 0.f) ? (1.0f / sqrtf(d)) : 0.f;
}

// single-block scan of g_cnt -> g_rowptr (inclusive shifted), g_fill (exclusive)
__global__ void k_scan() {
    __shared__ int sb[1024];
    __shared__ int carry;
    int t = threadIdx.x;
    if (t == 0) { carry = 0; g_rowptr[0] = 0; }
    __syncthreads();
    for (int base = 0; base < Nn; base += 1024) {
        int i = base + t;
        int v = (i < Nn) ? g_cnt[i] : 0;
        sb[t] = v;
        __syncthreads();
        for (int off = 1; off < 1024; off <<= 1) {
            int xv = (t >= off) ? sb[t - off] : 0;
            __syncthreads();
            sb[t] += xv;
            __syncthreads();
        }
        int incl = sb[t] + carry;
        if (i < Nn) { g_rowptr[i + 1] = incl; g_fill[i] = incl - v; }
        __syncthreads();
        if (t == 1023) carry = incl;
        __syncthreads();
    }
}

__global__ void k_csr(const void* __restrict__ ei,
                      const float* __restrict__ ew) {
    int e = blockIdx.x * blockDim.x + threadIdx.x;
    if (e >= Ee) return;
    int s, d;
    load_edge(ei, e, s, d);
    float w  = ew[e];
    float wz = (s == d) ? 0.f : w;
    float nw = -g_dinv[s] * wz * g_dinv[d];
    int pos = atomicAdd(&g_fill[d], 1);
    g_csrc[pos] = s;
    g_cw[pos]   = nw;
}

// ---------------- propagation (pull, CSR-by-dst) ------------------------------
__device__ __forceinline__ void prop64_core(const float* __restrict__ vin,
                                            const float* __restrict__ sub,
                                            float* __restrict__ vout,
                                            bool fuse) {
    int w = (blockIdx.x * blockDim.x + threadIdx.x) >> 5;
    if (w >= Nn) return;
    int lane = threadIdx.x & 31;
    int beg = g_rowptr[w], end = g_rowptr[w + 1];
    float a0 = 0.f, a1 = 0.f;
    int e = beg;
    for (; e + 1 < end; e += 2) {
        int   s0 = g_csrc[e],   s1 = g_csrc[e + 1];
        float w0 = g_cw[e],     w1 = g_cw[e + 1];
        float v00 = vin[s0 * 64 + lane];
        float v01 = vin[s0 * 64 + 32 + lane];
        float v10 = vin[s1 * 64 + lane];
        float v11 = vin[s1 * 64 + 32 + lane];
        a0 = fmaf(w0, v00, fmaf(w1, v10, a0));
        a1 = fmaf(w0, v01, fmaf(w1, v11, a1));
    }
    if (e < end) {
        int s = g_csrc[e]; float ww = g_cw[e];
        a0 = fmaf(ww, vin[s * 64 + lane], a0);
        a1 = fmaf(ww, vin[s * 64 + 32 + lane], a1);
    }
    if (fuse) {
        a0 = 2.f * a0 - sub[w * 64 + lane];
        a1 = 2.f * a1 - sub[w * 64 + 32 + lane];
    }
    vout[w * 64 + lane]      = a0;
    vout[w * 64 + 32 + lane] = a1;
}

__device__ __forceinline__ void prop16_core(const float* __restrict__ vin,
                                            const float* __restrict__ sub,
                                            float* __restrict__ vout,
                                            bool fuse) {
    int t = blockIdx.x * blockDim.x + threadIdx.x;
    int row = t >> 4, c = t & 15;
    if (row >= Nn) return;
    int beg = g_rowptr[row], end = g_rowptr[row + 1];
    float a = 0.f;
    int e = beg;
    for (; e + 1 < end; e += 2) {
        int s0 = g_csrc[e], s1 = g_csrc[e + 1];
        a = fmaf(g_cw[e], vin[s0 * 16 + c], fmaf(g_cw[e + 1], vin[s1 * 16 + c], a));
    }
    if (e < end) a = fmaf(g_cw[e], vin[g_csrc[e] * 16 + c], a);
    if (fuse) a = 2.f * a - sub[row * 16 + c];
    vout[row * 16 + c] = a;
}

__global__ void k_prop_x1(const float* __restrict__ x)  { prop16_core(x,     nullptr, g_tx1, false); }
__global__ void k_prop_x2(const float* __restrict__ x)  { prop16_core(g_tx1, x,       g_tx2, true ); }
__global__ void k_prop_h1(const float* __restrict__ h0) { prop64_core(h0,    nullptr, g_th1, false); }
__global__ void k_prop_h2(const float* __restrict__ h0) { prop64_core(g_th1, h0,      g_th2, true ); }
__global__ void k_prop_r1()                             { prop64_core(g_hr,  nullptr, g_tr1, false); }
__global__ void k_prop_r2()                             { prop64_core(g_tr1, g_hr,    g_tr2, true ); }

// ---------------- GEMM: x-path [N,48] @ [48,192] -> Xpre ----------------------
// blockDim = 192 (one col per thread), 16 rows per CTA
__global__ void k_gemm_x(const float* __restrict__ x,
                         const float* __restrict__ Wx,
                         const float* __restrict__ bx) {
    __shared__ float sA[16][48];
    int tid  = threadIdx.x;
    int row0 = blockIdx.x * 16;
    for (int i = tid; i < 16 * 48; i += 192) {
        int r = i / 48, kk = i % 48;
        float v;
        if (kk < 16)      v = x    [(row0 + r) * 16 + kk];
        else if (kk < 32) v = g_tx1[(row0 + r) * 16 + (kk - 16)];
        else              v = g_tx2[(row0 + r) * 16 + (kk - 32)];
        sA[r][kk] = v;
    }
    __syncthreads();
    int g = tid >> 6, co = tid & 63;
    float acc[16];
#pragma unroll
    for (int r = 0; r < 16; r++) acc[r] = 0.f;
    const float* Wg = Wx + (g * 48) * 64 + co;
    for (int kk = 0; kk < 48; kk += 4) {
        float w0 = Wg[(kk + 0) * 64];
        float w1 = Wg[(kk + 1) * 64];
        float w2 = Wg[(kk + 2) * 64];
        float w3 = Wg[(kk + 3) * 64];
#pragma unroll
        for (int r = 0; r < 16; r++) {
            float4 a = *(const float4*)&sA[r][kk];
            acc[r] = fmaf(a.x, w0, fmaf(a.y, w1, fmaf(a.z, w2, fmaf(a.w, w3, acc[r]))));
        }
    }
    float b = bx[g * 64 + co];
#pragma unroll
    for (int r = 0; r < 16; r++)
        g_xpre[(row0 + r) * 192 + tid] = acc[r] + b;
}

// ---------------- GEMM: h0-path -> z, r (fused sigmoid + hr) ------------------
// blockDim = 128 (cols z|r), 16 rows per CTA
__global__ void k_gemm_zr(const float* __restrict__ h0,
                          const float* __restrict__ Wh,
                          const float* __restrict__ bh) {
    __shared__ float sA[16][192];
    int tid  = threadIdx.x;
    int row0 = blockIdx.x * 16;
    for (int i = tid; i < 16 * 192; i += 128) {
        int r = i / 192, kk = i % 192;
        float v;
        if (kk < 64)       v = h0   [(row0 + r) * 64 + kk];
        else if (kk < 128) v = g_th1[(row0 + r) * 64 + (kk - 64)];
        else               v = g_th2[(row0 + r) * 64 + (kk - 128)];
        sA[r][kk] = v;
    }
    __syncthreads();
    int g = tid >> 6, co = tid & 63;
    float acc[16];
#pragma unroll
    for (int r = 0; r < 16; r++) acc[r] = 0.f;
    const float* Wg = Wh + (g * 192) * 64 + co;
    for (int kk = 0; kk < 192; kk += 4) {
        float w0 = Wg[(kk + 0) * 64];
        float w1 = Wg[(kk + 1) * 64];
        float w2 = Wg[(kk + 2) * 64];
        float w3 = Wg[(kk + 3) * 64];
#pragma unroll
        for (int r = 0; r < 16; r++) {
            float4 a = *(const float4*)&sA[r][kk];
            acc[r] = fmaf(a.x, w0, fmaf(a.y, w1, fmaf(a.z, w2, fmaf(a.w, w3, acc[r]))));
        }
    }
    float b = bh[g * 64 + co];
#pragma unroll
    for (int r = 0; r < 16; r++) {
        int row = row0 + r;
        float val = acc[r] + b + g_xpre[row * 192 + tid];
        float s = 1.0f / (1.0f + expf(-val));
        if (g == 0) g_z[row * 64 + co] = s;
        else        g_hr[row * 64 + co] = s * h0[row * 64 + co];
    }
}

// ---------------- GEMM: hr-path -> htil, h (fused tanh + GRU blend) ----------
// blockDim = 128: co = tid&63, row-half = tid>>6; 16 rows per CTA
__global__ void k_gemm_til(const float* __restrict__ h0,
                           const float* __restrict__ Wh,
                           const float* __restrict__ bh,
                           float* __restrict__ hout) {
    __shared__ float sA[16][192];
    int tid  = threadIdx.x;
    int row0 = blockIdx.x * 16;
    for (int i = tid; i < 16 * 192; i += 128) {
        int r = i / 192, kk = i % 192;
        float v;
        if (kk < 64)       v = g_hr [(row0 + r) * 64 + kk];
        else if (kk < 128) v = g_tr1[(row0 + r) * 64 + (kk - 64)];
        else               v = g_tr2[(row0 + r) * 64 + (kk - 128)];
        sA[r][kk] = v;
    }
    __syncthreads();
    int co = tid & 63, rh = tid >> 6;
    float acc[8];
#pragma unroll
    for (int r = 0; r < 8; r++) acc[r] = 0.f;
    const float* Wg = Wh + (2 * 192) * 64 + co;
    for (int kk = 0; kk < 192; kk += 4) {
        float w0 = Wg[(kk + 0) * 64];
        float w1 = Wg[(kk + 1) * 64];
        float w2 = Wg[(kk + 2) * 64];
        float w3 = Wg[(kk + 3) * 64];
#pragma unroll
        for (int r = 0; r < 8; r++) {
            float4 a = *(const float4*)&sA[rh * 8 + r][kk];
            acc[r] = fmaf(a.x, w0, fmaf(a.y, w1, fmaf(a.z, w2, fmaf(a.w, w3, acc[r]))));
        }
    }
    float b = bh[128 + co];
#pragma unroll
    for (int r = 0; r < 8; r++) {
        int row = row0 + rh * 8 + r;
        float pre = acc[r] + b + g_xpre[row * 192 + 128 + co];
        float ht  = tanhf(pre);
        float z   = g_z[row * 64 + co];
        float hv  = z * h0[row * 64 + co] + (1.0f - z) * ht;
        hout[row * 64 + co] = hv;
    }
}

// ---------------- final linear: y = relu(h) @ Wlin + blin ---------------------
__global__ void k_ylin(const float* __restrict__ h,
                       const float* __restrict__ Wlin,
                       const float* __restrict__ blin,
                       float* __restrict__ y) {
    __shared__ float sW[64 * 7];
    __shared__ float sb[7];
    int t = threadIdx.x;
    for (int i = t; i < 64 * 7; i += blockDim.x) sW[i] = Wlin[i];
    if (t < 7) sb[t] = blin[t];
    __syncthreads();
    int warp = (blockIdx.x * blockDim.x + t) >> 5;
    int lane = t & 31;
    if (warp >= Nn) return;
    float h0v = fmaxf(h[warp * 64 + lane], 0.f);
    float h1v = fmaxf(h[warp * 64 + 32 + lane], 0.f);
#pragma unroll
    for (int j = 0; j < 7; j++) {
        float p = h0v * sW[lane * 7 + j] + h1v * sW[(lane + 32) * 7 + j];
#pragma unroll
        for (int o = 16; o > 0; o >>= 1) p += __shfl_down_sync(0xffffffffu, p, o);
        if (lane == 0) y[warp * 7 + j] = p + sb[j];
    }
}

// ---------------- launch ------------------------------------------------------
extern "C" void kernel_launch(void* const* d_in, const int* in_sizes, int n_in,
                              void* d_out, int out_size) {
    const float* x    = (const float*)d_in[0];
    const void*  ei   = d_in[1];               // int32 or int64 — detected on device
    const float* ew   = (const float*)d_in[2];
    const float* h0   = (const float*)d_in[3];
    const float* Wx   = (const float*)d_in[4];
    const float* Wh   = (const float*)d_in[5];
    const float* bx   = (const float*)d_in[6];
    const float* bh   = (const float*)d_in[7];
    const float* Wlin = (const float*)d_in[8];
    const float* blin = (const float*)d_in[9];
    float* out  = (float*)d_out;
    float* hout = out;
    float* yout = out + (size_t)Nn * 64;

    const int TB = 256;
    const int gN = (Nn + TB - 1) / TB;
    const int gE = (Ee + TB - 1) / TB;

    // dtype detection + normalization + CSR build
    k_detect<<<1, 32>>>((const unsigned*)ei);
    k_zero  <<<gN, TB>>>();
    k_degcnt<<<gE, TB>>>(ei, ew);
    k_dinv  <<<gN, TB>>>();
    k_scan  <<<1, 1024>>>();
    k_csr   <<<gE, TB>>>(ei, ew);

    // x-path Chebyshev + x GEMM
    k_prop_x1<<<(Nn * 16 + TB - 1) / TB, TB>>>(x);
    k_prop_x2<<<(Nn * 16 + TB - 1) / TB, TB>>>(x);
    k_gemm_x <<<Nn / 16, 192>>>(x, Wx, bx);

    // h0-path Chebyshev + z/r GEMM (fused sigmoid, hr = h0*r)
    k_prop_h1<<<(Nn * 32 + TB - 1) / TB, TB>>>(h0);
    k_prop_h2<<<(Nn * 32 + TB - 1) / TB, TB>>>(h0);
    k_gemm_zr<<<Nn / 16, 128>>>(h0, Wh, bh);

    // hr-path Chebyshev + htil GEMM (fused tanh + GRU blend -> h)
    k_prop_r1 <<<(Nn * 32 + TB - 1) / TB, TB>>>();
    k_prop_r2 <<<(Nn * 32 + TB - 1) / TB, TB>>>();
    k_gemm_til<<<Nn / 16, 128>>>(h0, Wh, bh, hout);

    // y = relu(h) @ Wlin + blin
    k_ylin<<<(Nn * 32 + TB - 1) / TB, TB>>>(hout, Wlin, blin, yout);
}